// round 15
// baseline (speedup 1.0000x reference)
#include <cuda_runtime.h>
#include <cuda_bf16.h>
#include <math.h>
#include <cstdint>

#define BB 512
#define TT 24
#define VV 30
#define SWID 752        // fp32 state row: x[0:250) m[250:750) pad
#define KB2 768         // base K (750 -> 768)
#define NPG 1280        // padded gate output cols
#define NTL 40          // tiles: 4 (m) x 10 (n), 128x128 each
#define NSEG 3          // k segments of 256
#define GU (NTL*NSEG)   // 120 work units
// stage layout: Ah 16KB | Al 16KB | Wh 16KB | Wl 16KB
#define OFF_AL 16384
#define OFF_WH 32768
#define STG_BYTES 65536
#define DSM_BYTES (3*STG_BYTES)   // 196608

// Head packed dims (fp32 CUDA-core path)
#define HW1 (752*512)
#define HW2 (512*320)
#define HW3 (320*256)
#define HW4 (256*128)
#define HW5 (128*64)
#define WH_TOT (HW1+HW2+HW3+HW4+HW5)

// -------- device scratch --------
__device__ __align__(16) __nv_bfloat16 g_Wt[6ULL*2*NPG*KB2];    // [l][plane][n][k]
__device__ __align__(16) __nv_bfloat16 g_Abf[2][2*BB*KB2];      // [pingpong][plane][row][k]
__device__ __align__(16) float g_part[NTL*3*128*128];           // partial slots (same bytes as before)
__device__ __align__(16) float g_bias[6][NPG];
__device__ __align__(16) float g_E[VV][NPG];
__device__ __align__(16) float g_state[2][BB*SWID];
__device__ __align__(16) float g_h0[BB*512];
__device__ __align__(16) float g_h1[BB*512];
__device__ __align__(16) float g_logits[BB*64];
__device__ __align__(16) float g_WH[WH_TOT];
__device__ __align__(16) float g_bH[512+320+256+128+64];

// ======================= helpers =======================
__device__ __forceinline__ uint32_t smem_u32(const void* p) {
    uint32_t a;
    asm("{ .reg .u64 t; cvta.to.shared.u64 t, %1; cvt.u32.u64 %0, t; }" : "=r"(a) : "l"(p));
    return a;
}
__device__ __forceinline__ void cp16(uint32_t dst, const void* src){
    asm volatile("cp.async.cg.shared.global [%0], [%1], 16;" :: "r"(dst), "l"(src) : "memory");
}
#define CP_COMMIT() asm volatile("cp.async.commit_group;" ::: "memory")
#define CP_WAIT1()  asm volatile("cp.async.wait_group 1;" ::: "memory")
#define CP_WAIT0()  asm volatile("cp.async.wait_group 0;" ::: "memory")

#define LDSM4(rg, addr) \
    asm volatile("ldmatrix.sync.aligned.m8n8.x4.shared.b16 {%0,%1,%2,%3}, [%4];" \
        : "=r"((rg)[0]),"=r"((rg)[1]),"=r"((rg)[2]),"=r"((rg)[3]) : "r"(addr))

__device__ __forceinline__ void mma_bf16(float* d, const uint32_t* a, uint32_t b0, uint32_t b1){
    asm volatile("mma.sync.aligned.m16n8k16.row.col.f32.bf16.bf16.f32 "
                 "{%0,%1,%2,%3}, {%4,%5,%6,%7}, {%8,%9}, {%0,%1,%2,%3};"
                 : "+f"(d[0]), "+f"(d[1]), "+f"(d[2]), "+f"(d[3])
                 : "r"(a[0]), "r"(a[1]), "r"(a[2]), "r"(a[3]), "r"(b0), "r"(b1));
}

// fast gate nonlinearities (MUFU.EX2 based; rel err ~1e-6)
__device__ __forceinline__ float fsig(float z){
    return 1.f / (1.f + __expf(-z));
}
__device__ __forceinline__ float ftanh(float z){
    return 1.f - 2.f / (__expf(2.f*z) + 1.f);
}

// ======================= packing kernels =======================
// Tiled transpose pack: grid (12 kt, 20 nt, 6 l), 256 threads.
__global__ void pack_wt(const float* __restrict__ w1_sv, const float* __restrict__ w1_mem,
                        const float* __restrict__ w1_sw,
                        const float* __restrict__ w_sv, const float* __restrict__ w_mem,
                        const float* __restrict__ w_sw)
{
    __shared__ __nv_bfloat16 sh[64][66];
    __shared__ __nv_bfloat16 sl[64][66];

    int kt = blockIdx.x, nt = blockIdx.y, l = blockIdx.z;
    int k0 = kt * 64, n0 = nt * 64;
    int tid = threadIdx.x;

    int ln = tid & 63, lk = tid >> 6;
    int n = n0 + ln;
    #pragma unroll 4
    for (int pass = 0; pass < 16; pass++){
        int k = lk + pass * 4;
        int kk = k0 + k;
        float w = 0.f;
        if (kk < 750 && n < 1250){
            if (n < 1000){
                int j = n >> 1;
                if (!(n & 1)) w = (l==0) ? w1_sw[kk*500+j]  : w_sw[(size_t)(l-1)*375000 + (size_t)kk*500 + j];
                else          w = (l==0) ? w1_mem[kk*500+j] : w_mem[(size_t)(l-1)*375000 + (size_t)kk*500 + j];
            } else {
                int j = n - 1000;
                w = (l==0) ? w1_sv[kk*250+j] : w_sv[(size_t)(l-1)*187500 + (size_t)kk*250 + j];
            }
        }
        __nv_bfloat16 h = __float2bfloat16(w);
        sh[ln][k] = h;
        sl[ln][k] = __float2bfloat16(w - __bfloat162float(h));
    }
    __syncthreads();

    int wk = tid & 63, wn = tid >> 6;
    size_t planeStride = (size_t)NPG * KB2;
    size_t baseHi = (size_t)l * 2 * planeStride;
    #pragma unroll 4
    for (int pass = 0; pass < 16; pass++){
        int nn = wn + pass * 4;
        size_t dst = baseHi + (size_t)(n0 + nn) * KB2 + k0 + wk;
        g_Wt[dst]               = sh[nn][wk];
        g_Wt[dst + planeStride] = sl[nn][wk];
    }
}

__global__ void pack_misc(const float* __restrict__ b1_sv, const float* __restrict__ b1_mem,
                          const float* __restrict__ b1_sw,
                          const float* __restrict__ b_sv, const float* __restrict__ b_mem,
                          const float* __restrict__ b_sw,
                          const float* __restrict__ w1_sv, const float* __restrict__ w1_mem,
                          const float* __restrict__ w1_sw,
                          const float* __restrict__ wp1, const float* __restrict__ bp1,
                          const float* __restrict__ wp2, const float* __restrict__ bp2,
                          const float* __restrict__ wp3, const float* __restrict__ bp3,
                          const float* __restrict__ wp4, const float* __restrict__ bp4,
                          const float* __restrict__ wp5, const float* __restrict__ bp5)
{
    long long idx = (long long)blockIdx.x * blockDim.x + threadIdx.x;
    const int S0 = 6*NPG;
    const int S1 = S0 + VV*NPG;
    const int S2 = S1 + 2*BB*SWID;
    const int S3 = S2 + WH_TOT;
    const int S4 = S3 + (512+320+256+128+64);
    const long long S5 = (long long)S4 + 2LL*2*BB*KB2/2;   // zero g_Abf as u32
    if (idx >= S5) return;
    if (idx < S0){
        int l = (int)(idx / NPG), c = (int)(idx % NPG);
        float v = 0.f;
        if (c < 1000){
            int j = c >> 1;
            if (!(c & 1)) v = (l==0) ? b1_sw[j]  : b_sw[(l-1)*500+j];
            else          v = (l==0) ? b1_mem[j] : b_mem[(l-1)*500+j];
        } else if (c < 1250){
            v = (l==0) ? b1_sv[c-1000] : b_sv[(l-1)*250 + (c-1000)];
        }
        g_bias[l][c] = v;
    } else if (idx < S1){
        int q = (int)(idx - S0); int vv = q / NPG, c = q % NPG;
        int k = 750 + vv;
        float v = 0.f;
        if (c < 1000){
            int j = c >> 1;
            v = (c & 1) ? w1_mem[k*500+j] : w1_sw[k*500+j];
        } else if (c < 1250){
            v = w1_sv[k*250 + (c-1000)];
        }
        g_E[vv][c] = v;
    } else if (idx < S2){
        ((float*)g_state)[idx - S1] = 0.f;
    } else if (idx < S3){
        int q = (int)(idx - S2);
        const int off1 = HW1, off2 = HW1+HW2, off3 = HW1+HW2+HW3, off4 = HW1+HW2+HW3+HW4;
        int l, qi;
        if      (q < off1){ l=0; qi=q; }
        else if (q < off2){ l=1; qi=q-off1; }
        else if (q < off3){ l=2; qi=q-off2; }
        else if (q < off4){ l=3; qi=q-off3; }
        else              { l=4; qi=q-off4; }
        const int Npd[5] = {512,320,256,128,64};
        const int Ks[5]  = {750,450,300,200,100};
        const int Ns[5]  = {450,300,200,100,30};
        const float* wp[5] = {wp1,wp2,wp3,wp4,wp5};
        int k = qi / Npd[l], c = qi % Npd[l];
        g_WH[q] = (k < Ks[l] && c < Ns[l]) ? wp[l][k*Ns[l]+c] : 0.f;
    } else if (idx < S4){
        int q = (int)(idx - S3);
        int l, c;
        if      (q < 512)  { l=0; c=q; }
        else if (q < 832)  { l=1; c=q-512; }
        else if (q < 1088) { l=2; c=q-832; }
        else if (q < 1216) { l=3; c=q-1088; }
        else               { l=4; c=q-1216; }
        const int Ns[5] = {450,300,200,100,30};
        const float* bp[5] = {bp1,bp2,bp3,bp4,bp5};
        g_bH[q] = (c < Ns[l]) ? bp[l][c] : 0.f;
    } else {
        ((uint32_t*)g_Abf)[idx - S4] = 0u;
    }
}

// ======================= gate GEMM: split-K, 128x128 tiles, 8 warps 32x64 =======================
__device__ __forceinline__ void load_chunk(uint32_t dstBase,
                                           const __nv_bfloat16* __restrict__ Ain,
                                           const __nv_bfloat16* __restrict__ Wt,
                                           int m0, int n0, int kb, int tid)
{
    // A: 2 planes x 128 rows x 8 (16B) = 2048 cp16, 8/thread
    #pragma unroll
    for (int pp = 0; pp < 8; pp++){
        int q = pp*256 + tid;
        int j = q & 7, r = (q >> 3) & 127, pl = q >> 10;
        const __nv_bfloat16* src = Ain + (size_t)pl*(BB*KB2) + (size_t)(m0 + r)*KB2 + kb + j*8;
        cp16(dstBase + pl*OFF_AL + (uint32_t)(r*128 + ((j*16) ^ ((r & 7) << 4))), src);
    }
    // B: 2 planes x 128 rows x 8 (16B) = 2048 cp16, 8/thread
    #pragma unroll
    for (int pp = 0; pp < 8; pp++){
        int q = pp*256 + tid;
        int j = q & 7, n = (q >> 3) & 127, pl = q >> 10;
        const __nv_bfloat16* src = Wt + (size_t)pl*(NPG*KB2) + (size_t)(n0 + n)*KB2 + kb + j*8;
        cp16(dstBase + OFF_WH + pl*16384 + (uint32_t)(n*128 + ((j*16) ^ ((n & 7) << 4))), src);
    }
}

__global__ __launch_bounds__(256, 1) void gate_gemm(
    const __nv_bfloat16* __restrict__ Ain,   // [2][512][768]
    const __nv_bfloat16* __restrict__ Wt,    // [2][1280][768]
    float* __restrict__ part)
{
    extern __shared__ char dsm[];
    uint32_t sb = smem_u32(dsm);

    int tid = threadIdx.x, wid = tid >> 5, lane = tid & 31;
    int wm = wid >> 1, wn = wid & 1;       // 4(m x32) x 2(n x64)
    int u = blockIdx.x;
    int tile = u / 3, seg = u % 3;
    int tm = tile / 10, tn = tile % 10;
    int m0 = tm * 128, n0 = tn * 128;
    int kb0 = seg * 256;

    int q = lane >> 3, r = lane & 7;
    uint32_t preA[2][2];
    #pragma unroll
    for (int pl = 0; pl < 2; pl++)
        #pragma unroll
        for (int mi = 0; mi < 2; mi++)
            preA[pl][mi] = pl*OFF_AL + (uint32_t)((wm*32 + mi*16 + (q&1)*8 + r) * 128);
    uint32_t preB[2][4];
    #pragma unroll
    for (int pl = 0; pl < 2; pl++)
        #pragma unroll
        for (int np = 0; np < 4; np++)
            preB[pl][np] = OFF_WH + pl*16384 + (uint32_t)((wn*64 + np*16 + (q>>1)*8 + r) * 128);
    uint32_t kxA[4], kxB[4];
    #pragma unroll
    for (int ks = 0; ks < 4; ks++){
        kxA[ks] = (uint32_t)((ks*32 + (q>>1)*16) ^ (r << 4));
        kxB[ks] = (uint32_t)((ks*32 + (q&1)*16) ^ (r << 4));
    }

    float acc[2][8][4];
    #pragma unroll
    for (int mi = 0; mi < 2; mi++)
        #pragma unroll
        for (int ni = 0; ni < 8; ni++)
            #pragma unroll
            for (int ee = 0; ee < 4; ee++) acc[mi][ni][ee] = 0.f;

#if __CUDA_ARCH__ >= 900
    cudaGridDependencySynchronize();   // PDL: Abf must be ready (precomputes above are independent)
#endif

    load_chunk(sb + 0*STG_BYTES, Ain, Wt, m0, n0, kb0 + 0,  tid); CP_COMMIT();
    load_chunk(sb + 1*STG_BYTES, Ain, Wt, m0, n0, kb0 + 64, tid); CP_COMMIT();

    for (int ch = 0; ch < 4; ch++){
        if (ch < 3) { CP_WAIT1(); } else { CP_WAIT0(); }
        __syncthreads();                 // chunk ch resident for all threads

        uint32_t ab = sb + (uint32_t)(ch % 3)*STG_BYTES;
        #pragma unroll
        for (int ks = 0; ks < 4; ks++){
            uint32_t ah[2][4], al[2][4], bh[4][4], bl[4][4];
            LDSM4(bh[0], ab + preB[0][0] + kxB[ks]);
            LDSM4(bh[1], ab + preB[0][1] + kxB[ks]);
            LDSM4(bh[2], ab + preB[0][2] + kxB[ks]);
            LDSM4(bh[3], ab + preB[0][3] + kxB[ks]);
            LDSM4(ah[0], ab + preA[0][0] + kxA[ks]);
            LDSM4(ah[1], ab + preA[0][1] + kxA[ks]);
            // term Ah*Wh
            #pragma unroll
            for (int mi = 0; mi < 2; mi++)
                #pragma unroll
                for (int np = 0; np < 4; np++){
                    mma_bf16(acc[mi][np*2+0], ah[mi], bh[np][0], bh[np][1]);
                    mma_bf16(acc[mi][np*2+1], ah[mi], bh[np][2], bh[np][3]);
                }
            LDSM4(bl[0], ab + preB[1][0] + kxB[ks]);
            LDSM4(bl[1], ab + preB[1][1] + kxB[ks]);
            LDSM4(bl[2], ab + preB[1][2] + kxB[ks]);
            LDSM4(bl[3], ab + preB[1][3] + kxB[ks]);
            // term Ah*Wl
            #pragma unroll
            for (int mi = 0; mi < 2; mi++)
                #pragma unroll
                for (int np = 0; np < 4; np++){
                    mma_bf16(acc[mi][np*2+0], ah[mi], bl[np][0], bl[np][1]);
                    mma_bf16(acc[mi][np*2+1], ah[mi], bl[np][2], bl[np][3]);
                }
            LDSM4(al[0], ab + preA[1][0] + kxA[ks]);
            LDSM4(al[1], ab + preA[1][1] + kxA[ks]);
            // term Al*Wh
            #pragma unroll
            for (int mi = 0; mi < 2; mi++)
                #pragma unroll
                for (int np = 0; np < 4; np++){
                    mma_bf16(acc[mi][np*2+0], al[mi], bh[np][0], bh[np][1]);
                    mma_bf16(acc[mi][np*2+1], al[mi], bh[np][2], bh[np][3]);
                }
        }
        __syncthreads();                 // all reads of this stage done
        if (ch + 2 < 4){
            load_chunk(sb + (uint32_t)((ch+2) % 3)*STG_BYTES, Ain, Wt, m0, n0, kb0 + (ch+2)*64, tid);
            CP_COMMIT();
        }
    }

    // write partial slot (slot = seg; always 3 contributors per tile)
    float* sp = part + (size_t)(tile*3 + seg) * 16384;
    #pragma unroll
    for (int mi = 0; mi < 2; mi++){
        #pragma unroll
        for (int ni = 0; ni < 8; ni++){
            int rr = wm*32 + mi*16 + (lane >> 2);
            int cc = wn*64 + ni*8 + (lane & 3)*2;
            *(float2*)&sp[rr*128 + cc]     = make_float2(acc[mi][ni][0], acc[mi][ni][1]);
            *(float2*)&sp[(rr+8)*128 + cc] = make_float2(acc[mi][ni][2], acc[mi][ni][3]);
        }
    }
}

// ======================= gate epilogue: 640 CTAs, 4 cols/thread, always 3 slots =======================
__global__ __launch_bounds__(256) void gate_epi(
    const float* __restrict__ bias,
    const float* __restrict__ E,             // null unless layer 0
    const int* __restrict__ lettersT,        // letters + t, stride TT
    const float* __restrict__ stateIn,
    float* __restrict__ stateOut,
    __nv_bfloat16* __restrict__ Aout,
    const float* __restrict__ part,
    int writeX)
{
#if __CUDA_ARCH__ >= 900
    cudaGridDependencySynchronize();         // PDL: part fully written by gate_gemm
#endif
    int bx = blockIdx.x, tid = threadIdx.x;
    int tile = bx >> 4, sub = bx & 15;       // 16 x 8-row slabs per 128x128 tile

    int tm = tile / 10, tn = tile % 10;
    int m0 = tm * 128 + sub * 8, n0g = tn * 128;
    const float* pb = part + (size_t)tile * 3 * 16384 + (size_t)sub * 8 * 128;

    int rl = tid >> 5;            // 0..7
    int cg = (tid & 31) * 4;      // 0..124
    int row = m0 + rl;
    int c = n0g + cg;

    const float* base = pb + rl*128 + cg;
    float4 t0 = *(const float4*)(base);
    float4 t1 = *(const float4*)(base + 16384);
    float4 t2 = *(const float4*)(base + 32768);
    float4 bz = *(const float4*)(bias + c);
    float z0 = t0.x + t1.x + t2.x + bz.x;
    float z1 = t0.y + t1.y + t2.y + bz.y;
    float z2 = t0.z + t1.z + t2.z + bz.z;
    float z3 = t0.w + t1.w + t2.w + bz.w;
    if (E){
        float4 ez = *(const float4*)(E + (size_t)lettersT[row*TT] * NPG + c);
        z0 += ez.x; z1 += ez.y; z2 += ez.z; z3 += ez.w;
    }

    __nv_bfloat16* AoutLo = Aout + (size_t)BB*KB2;
    if (c < 1000){
        int j = c >> 1;
        float2 mo = *(const float2*)(stateIn + (size_t)row*SWID + 250 + j);
        float sg0 = fsig(z0), sg1 = fsig(z2);
        float mn0 = mo.x*sg0 + ftanh(z1)*(1.f - sg0);
        float mn1 = mo.y*sg1 + ftanh(z3)*(1.f - sg1);
        *(float2*)(stateOut + (size_t)row*SWID + 250 + j) = make_float2(mn0, mn1);
        __nv_bfloat162 h = __floats2bfloat162_rn(mn0, mn1);
        *(__nv_bfloat162*)(Aout + (size_t)row*KB2 + 250 + j) = h;
        float lo0 = mn0 - __bfloat162float(__low2bfloat16(h));
        float lo1 = mn1 - __bfloat162float(__high2bfloat16(h));
        *(__nv_bfloat162*)(AoutLo + (size_t)row*KB2 + 250 + j) = __floats2bfloat162_rn(lo0, lo1);
    } else if (c < 1250){
        int k = c - 1000;
        if (c + 3 < 1250){
            float x0 = ftanh(z0), x1 = ftanh(z1), x2 = ftanh(z2), x3 = ftanh(z3);
            if (writeX) *(float4*)(stateOut + (size_t)row*SWID + k) = make_float4(x0,x1,x2,x3);
            __nv_bfloat162 h01 = __floats2bfloat162_rn(x0, x1);
            __nv_bfloat162 h23 = __floats2bfloat162_rn(x2, x3);
            uint2 hv = make_uint2(*(uint32_t*)&h01, *(uint32_t*)&h23);
            *(uint2*)(Aout + (size_t)row*KB2 + k) = hv;
            float l0 = x0 - __bfloat162float(__low2bfloat16(h01));
            float l1 = x1 - __bfloat162float(__high2bfloat16(h01));
            float l2 = x2 - __bfloat162float(__low2bfloat16(h23));
            float l3 = x3 - __bfloat162float(__high2bfloat16(h23));
            __nv_bfloat162 q01 = __floats2bfloat162_rn(l0, l1);
            __nv_bfloat162 q23 = __floats2bfloat162_rn(l2, l3);
            uint2 lv = make_uint2(*(uint32_t*)&q01, *(uint32_t*)&q23);
            *(uint2*)(AoutLo + (size_t)row*KB2 + k) = lv;
        } else {
            // c == 1248: 2 valid cols
            float x0 = ftanh(z0), x1 = ftanh(z1);
            if (writeX) *(float2*)(stateOut + (size_t)row*SWID + k) = make_float2(x0, x1);
            __nv_bfloat162 h = __floats2bfloat162_rn(x0, x1);
            *(__nv_bfloat162*)(Aout + (size_t)row*KB2 + k) = h;
            float l0 = x0 - __bfloat162float(__low2bfloat16(h));
            float l1 = x1 - __bfloat162float(__high2bfloat16(h));
            *(__nv_bfloat162*)(AoutLo + (size_t)row*KB2 + k) = __floats2bfloat162_rn(l0, l1);
        }
    }
}

// ======================= head GEMM (fp32 f32x2, 32x64 tiles) =======================
__device__ __forceinline__ unsigned long long dup_f32x2(float x){
    unsigned long long rr;
    asm("mov.b64 %0, {%1, %1};" : "=l"(rr) : "f"(x));
    return rr;
}
__device__ __forceinline__ void fma_f32x2(unsigned long long& d, unsigned long long a, unsigned long long b){
    asm("fma.rn.f32x2 %0, %1, %2, %0;" : "+l"(d) : "l"(a), "l"(b));
}
__device__ __forceinline__ float2 unpack_f32x2(unsigned long long v){
    float2 f;
    asm("mov.b64 {%0, %1}, %2;" : "=f"(f.x), "=f"(f.y) : "l"(v));
    return f;
}

template<int MODE>   // 1: tanh, 2: identity
__global__ __launch_bounds__(256) void head_gemm(
    const float* __restrict__ A, int lda,
    const float* __restrict__ W, int nld,
    const float* __restrict__ bias,
    int K,
    float* __restrict__ out, int ldo)
{
    __shared__ __align__(16) float As[2][16][36];
    __shared__ __align__(16) float Bs[2][16][64];

    int tid = threadIdx.x;
    int tx = tid & 15, ty = tid >> 4;
    int m0 = blockIdx.y * 32, n0 = blockIdx.x * 64;

    unsigned long long acc[2][2];
    acc[0][0] = 0ULL; acc[0][1] = 0ULL; acc[1][0] = 0ULL; acc[1][1] = 0ULL;

    int ar = tid >> 2;
    int ak = (tid & 3) * 4;
    int br = tid >> 4;
    int bc = (tid & 15) * 4;

    const float* Ap = A + (size_t)(m0 + (ar & 31)) * lda + ak;
    const float* Wp = W + (size_t)br * nld + n0 + bc;

    {
        if (tid < 128){
            float4 a = *(const float4*)Ap;
            As[0][ak+0][ar] = a.x; As[0][ak+1][ar] = a.y;
            As[0][ak+2][ar] = a.z; As[0][ak+3][ar] = a.w;
        }
        float4 b = *(const float4*)Wp;
        *(float4*)&Bs[0][br][bc] = b;
    }
    __syncthreads();

    int nk = K >> 4;
    for (int kt = 0; kt < nk; kt++){
        int cur = kt & 1;
        float4 an, bn;
        if (kt + 1 < nk){
            if (tid < 128) an = *(const float4*)(Ap + (kt+1)*16);
            bn = *(const float4*)(Wp + (size_t)(kt+1)*16*nld);
        }
        #pragma unroll
        for (int k = 0; k < 16; k++){
            ulonglong2 bp = *(const ulonglong2*)&Bs[cur][k][tx*4];
            float a0 = As[cur][k][ty*2+0];
            float a1 = As[cur][k][ty*2+1];
            unsigned long long d0 = dup_f32x2(a0);
            unsigned long long d1 = dup_f32x2(a1);
            fma_f32x2(acc[0][0], d0, bp.x); fma_f32x2(acc[0][1], d0, bp.y);
            fma_f32x2(acc[1][0], d1, bp.x); fma_f32x2(acc[1][1], d1, bp.y);
        }
        if (kt + 1 < nk){
            __syncthreads();
            int nxt = cur ^ 1;
            if (tid < 128){
                As[nxt][ak+0][ar] = an.x; As[nxt][ak+1][ar] = an.y;
                As[nxt][ak+2][ar] = an.z; As[nxt][ak+3][ar] = an.w;
            }
            *(float4*)&Bs[nxt][br][bc] = bn;
            __syncthreads();
        }
    }

    #pragma unroll
    for (int i = 0; i < 2; i++){
        int rr = m0 + ty*2 + i;
        #pragma unroll
        for (int j2 = 0; j2 < 2; j2++){
            int c = n0 + tx*4 + j2*2;
            float2 z = unpack_f32x2(acc[i][j2]);
            z.x += bias[c]; z.y += bias[c+1];
            if (MODE == 1){
                out[(size_t)rr*ldo + c]   = tanhf(z.x);
                out[(size_t)rr*ldo + c+1] = tanhf(z.y);
            } else {
                out[(size_t)rr*ldo + c]   = z.x;
                out[(size_t)rr*ldo + c+1] = z.y;
            }
        }
    }
}

// -------- softmax over 30 classes --------
__global__ void softmax_k(const float* __restrict__ logits, float* __restrict__ out){
    int gw = blockIdx.x * 8 + (threadIdx.x >> 5);
    int lane = threadIdx.x & 31;
    if (gw >= BB) return;
    float v = (lane < VV) ? logits[gw*64 + lane] : -3.0e38f;
    float mx = v;
    #pragma unroll
    for (int o = 16; o > 0; o >>= 1) mx = fmaxf(mx, __shfl_xor_sync(0xffffffffu, mx, o));
    float ee = (lane < VV) ? expf(v - mx) : 0.f;
    float sm = ee;
    #pragma unroll
    for (int o = 16; o > 0; o >>= 1) sm += __shfl_xor_sync(0xffffffffu, sm, o);
    if (lane < VV) out[gw*VV + lane] = ee / sm;
}

extern "C" void kernel_launch(void* const* d_in, const int* in_sizes, int n_in,
                              void* d_out, int out_size)
{
    (void)in_sizes; (void)n_in; (void)out_size;
    const int*   letters = (const int*)  d_in[0];
    const float* w1_sv   = (const float*)d_in[1];
    const float* b1_sv   = (const float*)d_in[2];
    const float* w1_mem  = (const float*)d_in[3];
    const float* b1_mem  = (const float*)d_in[4];
    const float* w1_sw   = (const float*)d_in[5];
    const float* b1_sw   = (const float*)d_in[6];
    const float* w_sv    = (const float*)d_in[7];
    const float* b_sv    = (const float*)d_in[8];
    const float* w_mem   = (const float*)d_in[9];
    const float* b_mem   = (const float*)d_in[10];
    const float* w_sw    = (const float*)d_in[11];
    const float* b_sw    = (const float*)d_in[12];
    const float* wp1     = (const float*)d_in[13];
    const float* bp1     = (const float*)d_in[14];
    const float* wp2     = (const float*)d_in[15];
    const float* bp2     = (const float*)d_in[16];
    const float* wp3     = (const float*)d_in[17];
    const float* bp3     = (const float*)d_in[18];
    const float* wp4     = (const float*)d_in[19];
    const float* bp4     = (const float*)d_in[20];
    const float* wp5     = (const float*)d_in[21];
    const float* bp5     = (const float*)d_in[22];

    static int smem_cfg = 0;
    if (!smem_cfg){
        cudaFuncSetAttribute(gate_gemm, cudaFuncAttributeMaxDynamicSharedMemorySize, DSM_BYTES);
        smem_cfg = 1;
    }

    __nv_bfloat16 *pWt, *pAbf;
    float *pBias, *pE, *pState, *pH0, *pH1, *pLog, *pWH, *pBH, *pPart;
    cudaGetSymbolAddress((void**)&pWt,    g_Wt);
    cudaGetSymbolAddress((void**)&pAbf,   g_Abf);
    cudaGetSymbolAddress((void**)&pBias,  g_bias);
    cudaGetSymbolAddress((void**)&pE,     g_E);
    cudaGetSymbolAddress((void**)&pState, g_state);
    cudaGetSymbolAddress((void**)&pH0,    g_h0);
    cudaGetSymbolAddress((void**)&pH1,    g_h1);
    cudaGetSymbolAddress((void**)&pLog,   g_logits);
    cudaGetSymbolAddress((void**)&pWH,    g_WH);
    cudaGetSymbolAddress((void**)&pBH,    g_bH);
    cudaGetSymbolAddress((void**)&pPart,  g_part);

    // pack weights (tiled transpose, hi/lo planes) + misc + zero state/activations
    {
        pack_wt<<<dim3(KB2/64, NPG/64, 6), 256>>>(w1_sv, w1_mem, w1_sw, w_sv, w_mem, w_sw);
        long long S5 = 6*NPG + VV*NPG + 2*BB*SWID + WH_TOT + (512+320+256+128+64) + 2LL*2*BB*KB2/2;
        pack_misc<<<(unsigned)((S5 + 255) / 256), 256>>>(b1_sv, b1_mem, b1_sw, b_sv, b_mem, b_sw,
                                                         w1_sv, w1_mem, w1_sw,
                                                         wp1, bp1, wp2, bp2, wp3, bp3, wp4, bp4, wp5, bp5);
    }

    // PDL launch configs for the gate chain
    cudaLaunchAttribute pdlAttr[1];
    pdlAttr[0].id = cudaLaunchAttributeProgrammaticStreamSerialization;
    pdlAttr[0].val.programmaticStreamSerializationAllowed = 1;

    cudaLaunchConfig_t cfgG = {};
    cfgG.gridDim = dim3(GU, 1, 1);
    cfgG.blockDim = dim3(256, 1, 1);
    cfgG.dynamicSmemBytes = DSM_BYTES;
    cfgG.attrs = pdlAttr;
    cfgG.numAttrs = 1;

    cudaLaunchConfig_t cfgE = {};
    cfgE.gridDim = dim3(NTL*16, 1, 1);
    cfgE.blockDim = dim3(256, 1, 1);
    cfgE.dynamicSmemBytes = 0;
    cfgE.attrs = pdlAttr;
    cfgE.numAttrs = 1;

    // 24 steps x 6 gates: split-K GEMM + wide vectorized epilogue (PDL-chained)
    for (int g = 0; g < TT*6; g++){
        int t = g / 6, l = g % 6;
        int cur = g & 1, nxt = cur ^ 1;
        const float* Ept = (l == 0) ? pE : nullptr;
        const int*   lt  = (l == 0) ? letters + t : letters;
        cudaLaunchKernelEx(&cfgG, gate_gemm,
            (const __nv_bfloat16*)(pAbf + (size_t)cur*2*BB*KB2),
            (const __nv_bfloat16*)(pWt  + (size_t)l*2*NPG*KB2),
            pPart);
        cudaLaunchKernelEx(&cfgE, gate_epi,
            (const float*)(pBias + (size_t)l*NPG),
            (const float*)Ept, (const int*)lt,
            (const float*)(pState + (size_t)cur*BB*SWID),
            pState + (size_t)nxt*BB*SWID,
            pAbf + (size_t)nxt*2*BB*KB2,
            (const float*)pPart,
            (g == TT*6-1) ? 1 : 0);
    }

    // head: 750->450->300->200->100->30 (padded), 32-row tiles for occupancy
    head_gemm<1><<<dim3(8,16), 256>>>(pState, SWID, pWH,                   512, pBH,      752, pH0, 512);
    head_gemm<1><<<dim3(5,16), 256>>>(pH0,    512,  pWH + HW1,             320, pBH+512,  512, pH1, 320);
    head_gemm<1><<<dim3(4,16), 256>>>(pH1,    320,  pWH + HW1+HW2,         256, pBH+832,  320, pH0, 256);
    head_gemm<1><<<dim3(2,16), 256>>>(pH0,    256,  pWH + HW1+HW2+HW3,     128, pBH+1088, 256, pH1, 128);
    head_gemm<2><<<dim3(1,16), 256>>>(pH1,    128,  pWH + HW1+HW2+HW3+HW4,  64, pBH+1216, 128, pLog, 64);

    softmax_k<<<BB/8, 256>>>(pLog, (float*)d_out);
}

// round 16
// speedup vs baseline: 1.0210x; 1.0210x over previous
#include <cuda_runtime.h>
#include <cuda_bf16.h>
#include <math.h>
#include <cstdint>

#define BB 512
#define TT 24
#define VV 30
#define SWID 752        // fp32 state row: x[0:250) m[250:750) pad
#define KB2 768         // base K (750 -> 768)
#define NPG 1280        // padded gate output cols
#define NT 80           // tiles: 4 (m) x 20 (n)
#define NCHT 12         // k64 chunks per tile
#define GITER 960       // NT * NCHT
#define PCTA 148
// stage layout: Ah 16KB | Al 16KB | Wh 8KB | Wl 8KB
#define OFF_AL 16384
#define OFF_WH 32768
#define STG_BYTES 49152
#define DSM_BYTES (4*STG_BYTES)   // 196608

// Head packed dims (fp32 CUDA-core path)
#define HW1 (752*512)
#define HW2 (512*320)
#define HW3 (320*256)
#define HW4 (256*128)
#define HW5 (128*64)
#define WH_TOT (HW1+HW2+HW3+HW4+HW5)

// -------- device scratch --------
__device__ __align__(16) __nv_bfloat16 g_Wt[6ULL*2*NPG*KB2];    // [l][plane][n][k]
__device__ __align__(16) __nv_bfloat16 g_Abf[2][2*BB*KB2];      // [pingpong][plane][row][k]
__device__ __align__(16) float g_part[NT*3*128*64];             // partial slots
__device__ __align__(16) float g_bias[6][NPG];
__device__ __align__(16) float g_E[VV][NPG];
__device__ __align__(16) float g_state[2][BB*SWID];
__device__ __align__(16) float g_h0[BB*512];
__device__ __align__(16) float g_h1[BB*512];
__device__ __align__(16) float g_logits[BB*64];
__device__ __align__(16) float g_WH[WH_TOT];
__device__ __align__(16) float g_bH[512+320+256+128+64];

// ======================= helpers =======================
__device__ __forceinline__ uint32_t smem_u32(const void* p) {
    uint32_t a;
    asm("{ .reg .u64 t; cvta.to.shared.u64 t, %1; cvt.u32.u64 %0, t; }" : "=r"(a) : "l"(p));
    return a;
}
__device__ __forceinline__ void cp16(uint32_t dst, const void* src){
    asm volatile("cp.async.cg.shared.global [%0], [%1], 16;" :: "r"(dst), "l"(src) : "memory");
}
#define CP_COMMIT() asm volatile("cp.async.commit_group;" ::: "memory")
#define CP_WAIT2()  asm volatile("cp.async.wait_group 2;" ::: "memory")

#define LDSM4(rg, addr) \
    asm volatile("ldmatrix.sync.aligned.m8n8.x4.shared.b16 {%0,%1,%2,%3}, [%4];" \
        : "=r"((rg)[0]),"=r"((rg)[1]),"=r"((rg)[2]),"=r"((rg)[3]) : "r"(addr))

__device__ __forceinline__ void mma_bf16(float* d, const uint32_t* a, uint32_t b0, uint32_t b1){
    asm volatile("mma.sync.aligned.m16n8k16.row.col.f32.bf16.bf16.f32 "
                 "{%0,%1,%2,%3}, {%4,%5,%6,%7}, {%8,%9}, {%0,%1,%2,%3};"
                 : "+f"(d[0]), "+f"(d[1]), "+f"(d[2]), "+f"(d[3])
                 : "r"(a[0]), "r"(a[1]), "r"(a[2]), "r"(a[3]), "r"(b0), "r"(b1));
}

// fast gate nonlinearities (MUFU.EX2 based; rel err ~1e-6)
__device__ __forceinline__ float fsig(float z){
    return 1.f / (1.f + __expf(-z));
}
__device__ __forceinline__ float ftanh(float z){
    return 1.f - 2.f / (__expf(2.f*z) + 1.f);
}

// ======================= packing kernels =======================
// Tiled transpose pack: grid (12 kt, 20 nt, 6 l), 256 threads.
__global__ void pack_wt(const float* __restrict__ w1_sv, const float* __restrict__ w1_mem,
                        const float* __restrict__ w1_sw,
                        const float* __restrict__ w_sv, const float* __restrict__ w_mem,
                        const float* __restrict__ w_sw)
{
    __shared__ __nv_bfloat16 sh[64][66];
    __shared__ __nv_bfloat16 sl[64][66];

    int kt = blockIdx.x, nt = blockIdx.y, l = blockIdx.z;
    int k0 = kt * 64, n0 = nt * 64;
    int tid = threadIdx.x;

    int ln = tid & 63, lk = tid >> 6;
    int n = n0 + ln;
    #pragma unroll 4
    for (int pass = 0; pass < 16; pass++){
        int k = lk + pass * 4;
        int kk = k0 + k;
        float w = 0.f;
        if (kk < 750 && n < 1250){
            if (n < 1000){
                int j = n >> 1;
                if (!(n & 1)) w = (l==0) ? w1_sw[kk*500+j]  : w_sw[(size_t)(l-1)*375000 + (size_t)kk*500 + j];
                else          w = (l==0) ? w1_mem[kk*500+j] : w_mem[(size_t)(l-1)*375000 + (size_t)kk*500 + j];
            } else {
                int j = n - 1000;
                w = (l==0) ? w1_sv[kk*250+j] : w_sv[(size_t)(l-1)*187500 + (size_t)kk*250 + j];
            }
        }
        __nv_bfloat16 h = __float2bfloat16(w);
        sh[ln][k] = h;
        sl[ln][k] = __float2bfloat16(w - __bfloat162float(h));
    }
    __syncthreads();

    int wk = tid & 63, wn = tid >> 6;
    size_t planeStride = (size_t)NPG * KB2;
    size_t baseHi = (size_t)l * 2 * planeStride;
    #pragma unroll 4
    for (int pass = 0; pass < 16; pass++){
        int nn = wn + pass * 4;
        size_t dst = baseHi + (size_t)(n0 + nn) * KB2 + k0 + wk;
        g_Wt[dst]               = sh[nn][wk];
        g_Wt[dst + planeStride] = sl[nn][wk];
    }
}

__global__ void pack_misc(const float* __restrict__ b1_sv, const float* __restrict__ b1_mem,
                          const float* __restrict__ b1_sw,
                          const float* __restrict__ b_sv, const float* __restrict__ b_mem,
                          const float* __restrict__ b_sw,
                          const float* __restrict__ w1_sv, const float* __restrict__ w1_mem,
                          const float* __restrict__ w1_sw,
                          const float* __restrict__ wp1, const float* __restrict__ bp1,
                          const float* __restrict__ wp2, const float* __restrict__ bp2,
                          const float* __restrict__ wp3, const float* __restrict__ bp3,
                          const float* __restrict__ wp4, const float* __restrict__ bp4,
                          const float* __restrict__ wp5, const float* __restrict__ bp5)
{
    long long idx = (long long)blockIdx.x * blockDim.x + threadIdx.x;
    const int S0 = 6*NPG;
    const int S1 = S0 + VV*NPG;
    const int S2 = S1 + 2*BB*SWID;
    const int S3 = S2 + WH_TOT;
    const int S4 = S3 + (512+320+256+128+64);
    const long long S5 = (long long)S4 + 2LL*2*BB*KB2/2;   // zero g_Abf as u32
    if (idx >= S5) return;
    if (idx < S0){
        int l = (int)(idx / NPG), c = (int)(idx % NPG);
        float v = 0.f;
        if (c < 1000){
            int j = c >> 1;
            if (!(c & 1)) v = (l==0) ? b1_sw[j]  : b_sw[(l-1)*500+j];
            else          v = (l==0) ? b1_mem[j] : b_mem[(l-1)*500+j];
        } else if (c < 1250){
            v = (l==0) ? b1_sv[c-1000] : b_sv[(l-1)*250 + (c-1000)];
        }
        g_bias[l][c] = v;
    } else if (idx < S1){
        int q = (int)(idx - S0); int vv = q / NPG, c = q % NPG;
        int k = 750 + vv;
        float v = 0.f;
        if (c < 1000){
            int j = c >> 1;
            v = (c & 1) ? w1_mem[k*500+j] : w1_sw[k*500+j];
        } else if (c < 1250){
            v = w1_sv[k*250 + (c-1000)];
        }
        g_E[vv][c] = v;
    } else if (idx < S2){
        ((float*)g_state)[idx - S1] = 0.f;
    } else if (idx < S3){
        int q = (int)(idx - S2);
        const int off1 = HW1, off2 = HW1+HW2, off3 = HW1+HW2+HW3, off4 = HW1+HW2+HW3+HW4;
        int l, qi;
        if      (q < off1){ l=0; qi=q; }
        else if (q < off2){ l=1; qi=q-off1; }
        else if (q < off3){ l=2; qi=q-off2; }
        else if (q < off4){ l=3; qi=q-off3; }
        else              { l=4; qi=q-off4; }
        const int Npd[5] = {512,320,256,128,64};
        const int Ks[5]  = {750,450,300,200,100};
        const int Ns[5]  = {450,300,200,100,30};
        const float* wp[5] = {wp1,wp2,wp3,wp4,wp5};
        int k = qi / Npd[l], c = qi % Npd[l];
        g_WH[q] = (k < Ks[l] && c < Ns[l]) ? wp[l][k*Ns[l]+c] : 0.f;
    } else if (idx < S4){
        int q = (int)(idx - S3);
        int l, c;
        if      (q < 512)  { l=0; c=q; }
        else if (q < 832)  { l=1; c=q-512; }
        else if (q < 1088) { l=2; c=q-832; }
        else if (q < 1216) { l=3; c=q-1088; }
        else               { l=4; c=q-1216; }
        const int Ns[5] = {450,300,200,100,30};
        const float* bp[5] = {bp1,bp2,bp3,bp4,bp5};
        g_bH[q] = (c < Ns[l]) ? bp[l][c] : 0.f;
    } else {
        ((uint32_t*)g_Abf)[idx - S4] = 0u;
    }
}

// ======================= gate GEMM: stream-K (pure), HMMA + ldmatrix =======================
__device__ __forceinline__ void load_chunk_W(uint32_t dstBase,
                                             const __nv_bfloat16* __restrict__ Wt,
                                             int it, int tid)
{
    int tile = it / NCHT;
    int kb = (it % NCHT) * 64;
    int n0 = (tile % 20) * 64;
    #pragma unroll
    for (int pp = 0; pp < 4; pp++){
        int q = pp*256 + tid;
        int j = q & 7, n = (q >> 3) & 63, pl = q >> 9;
        const __nv_bfloat16* src = Wt + (size_t)pl*(NPG*KB2) + (size_t)(n0 + n)*KB2 + kb + j*8;
        cp16(dstBase + OFF_WH + pl*8192 + (uint32_t)(n*128 + ((j*16) ^ ((n & 7) << 4))), src);
    }
}

__device__ __forceinline__ void load_chunk_A(uint32_t dstBase,
                                             const __nv_bfloat16* __restrict__ Ain,
                                             int it, int tid)
{
    int tile = it / NCHT;
    int kb = (it % NCHT) * 64;
    int m0 = (tile / 20) * 128;
    #pragma unroll
    for (int pp = 0; pp < 8; pp++){
        int q = pp*256 + tid;
        int j = q & 7, r = (q >> 3) & 127, pl = q >> 10;
        const __nv_bfloat16* src = Ain + (size_t)pl*(BB*KB2) + (size_t)(m0 + r)*KB2 + kb + j*8;
        cp16(dstBase + pl*OFF_AL + (uint32_t)(r*128 + ((j*16) ^ ((r & 7) << 4))), src);
    }
}

__device__ __forceinline__ void ldall(uint32_t f[8][4], uint32_t ab,
                                      const uint32_t preA[2][2], const uint32_t preB[2][2],
                                      uint32_t ka, uint32_t kb)
{
    LDSM4(f[0], ab + preA[0][0] + ka);
    LDSM4(f[1], ab + preA[0][1] + ka);
    LDSM4(f[2], ab + preB[0][0] + kb);
    LDSM4(f[3], ab + preB[0][1] + kb);
    LDSM4(f[4], ab + preA[1][0] + ka);
    LDSM4(f[5], ab + preA[1][1] + ka);
    LDSM4(f[6], ab + preB[1][0] + kb);
    LDSM4(f[7], ab + preB[1][1] + kb);
}

__device__ __forceinline__ void mma24(float acc[2][4][4], uint32_t f[8][4]){
    // Ah*Wh
    mma_bf16(acc[0][0], f[0], f[2][0], f[2][1]);
    mma_bf16(acc[0][1], f[0], f[2][2], f[2][3]);
    mma_bf16(acc[0][2], f[0], f[3][0], f[3][1]);
    mma_bf16(acc[0][3], f[0], f[3][2], f[3][3]);
    mma_bf16(acc[1][0], f[1], f[2][0], f[2][1]);
    mma_bf16(acc[1][1], f[1], f[2][2], f[2][3]);
    mma_bf16(acc[1][2], f[1], f[3][0], f[3][1]);
    mma_bf16(acc[1][3], f[1], f[3][2], f[3][3]);
    // Ah*Wl
    mma_bf16(acc[0][0], f[0], f[6][0], f[6][1]);
    mma_bf16(acc[0][1], f[0], f[6][2], f[6][3]);
    mma_bf16(acc[0][2], f[0], f[7][0], f[7][1]);
    mma_bf16(acc[0][3], f[0], f[7][2], f[7][3]);
    mma_bf16(acc[1][0], f[1], f[6][0], f[6][1]);
    mma_bf16(acc[1][1], f[1], f[6][2], f[6][3]);
    mma_bf16(acc[1][2], f[1], f[7][0], f[7][1]);
    mma_bf16(acc[1][3], f[1], f[7][2], f[7][3]);
    // Al*Wh
    mma_bf16(acc[0][0], f[4], f[2][0], f[2][1]);
    mma_bf16(acc[0][1], f[4], f[2][2], f[2][3]);
    mma_bf16(acc[0][2], f[4], f[3][0], f[3][1]);
    mma_bf16(acc[0][3], f[4], f[3][2], f[3][3]);
    mma_bf16(acc[1][0], f[5], f[2][0], f[2][1]);
    mma_bf16(acc[1][1], f[5], f[2][2], f[2][3]);
    mma_bf16(acc[1][2], f[5], f[3][0], f[3][1]);
    mma_bf16(acc[1][3], f[5], f[3][2], f[3][3]);
}

__global__ __launch_bounds__(256, 1) void gate_gemm(
    const __nv_bfloat16* __restrict__ Ain,   // [2][512][768]
    const __nv_bfloat16* __restrict__ Wt,    // [2][1280][768]
    float* __restrict__ part)
{
    extern __shared__ char dsm[];
    uint32_t sb = smem_u32(dsm);

    int tid = threadIdx.x, wid = tid >> 5, lane = tid & 31;
    int wm = wid >> 1, wn = wid & 1;
    int p = blockIdx.x;
    int s = p * GITER / PCTA;
    int e = (p + 1) * GITER / PCTA;

    int q = lane >> 3, r = lane & 7;
    uint32_t preA[2][2];
    #pragma unroll
    for (int pl = 0; pl < 2; pl++)
        #pragma unroll
        for (int mi = 0; mi < 2; mi++)
            preA[pl][mi] = pl*OFF_AL + (uint32_t)((wm*32 + mi*16 + (q&1)*8 + r) * 128);
    uint32_t preB[2][2];
    #pragma unroll
    for (int pl = 0; pl < 2; pl++)
        #pragma unroll
        for (int np = 0; np < 2; np++)
            preB[pl][np] = OFF_WH + pl*8192 + (uint32_t)((wn*32 + np*16 + (q>>1)*8 + r) * 128);
    uint32_t kxA[4], kxB[4];
    #pragma unroll
    for (int ks = 0; ks < 4; ks++){
        kxA[ks] = (uint32_t)((ks*32 + (q>>1)*16) ^ (r << 4));
        kxB[ks] = (uint32_t)((ks*32 + (q&1)*16) ^ (r << 4));
    }

    float acc[2][4][4];
    #pragma unroll
    for (int mi = 0; mi < 2; mi++)
        #pragma unroll
        for (int ni = 0; ni < 4; ni++)
            #pragma unroll
            for (int ee = 0; ee < 4; ee++) acc[mi][ni][ee] = 0.f;

    // --- PDL prelaunch zone: weight tiles are independent of the previous kernel ---
    load_chunk_W(sb + (uint32_t)(s & 3)*STG_BYTES, Wt, s, tid);       CP_COMMIT();  // g0
    load_chunk_W(sb + (uint32_t)((s+1) & 3)*STG_BYTES, Wt, s+1, tid); CP_COMMIT();  // g1

#if __CUDA_ARCH__ >= 900
    cudaGridDependencySynchronize();   // Abf (activations) must be ready
#endif

    load_chunk_A(sb + (uint32_t)(s & 3)*STG_BYTES, Ain, s, tid);       CP_COMMIT(); // g2
    load_chunk_A(sb + (uint32_t)((s+1) & 3)*STG_BYTES, Ain, s+1, tid); CP_COMMIT(); // g3

    for (int it = s; it < e; it++){
        if (it + 2 < e){
            load_chunk_W(sb + (uint32_t)((it+2) & 3)*STG_BYTES, Wt, it+2, tid);
            load_chunk_A(sb + (uint32_t)((it+2) & 3)*STG_BYTES, Ain, it+2, tid);
        }
        CP_COMMIT();
        CP_WAIT2();            // in-order groups: all but the 2 newest retired -> chunk it resident
        __syncthreads();

        uint32_t ab = sb + (uint32_t)(it & 3)*STG_BYTES;
        uint32_t f[2][8][4];
        ldall(f[0], ab, preA, preB, kxA[0], kxB[0]);
        #pragma unroll
        for (int ks = 0; ks < 4; ks++){
            if (ks < 3) ldall(f[(ks+1)&1], ab, preA, preB, kxA[ks+1], kxB[ks+1]);
            mma24(acc, f[ks&1]);
        }

        if (it + 1 == e || (it + 1) % NCHT == 0){
            int tile = it / NCHT;
            int tstart = tile * NCHT;
            int c0 = (s > tstart ? s : tstart) - tstart;
            int slot = (c0 == 0) ? 0 : ((c0 < 6) ? 1 : 2);
            float* sp = part + (size_t)(tile*3 + slot) * 8192;
            #pragma unroll
            for (int mi = 0; mi < 2; mi++){
                #pragma unroll
                for (int ni = 0; ni < 4; ni++){
                    int rr = wm*32 + mi*16 + (lane >> 2);
                    int cc = wn*32 + ni*8 + (lane & 3)*2;
                    *(float2*)&sp[rr*64 + cc]     = make_float2(acc[mi][ni][0], acc[mi][ni][1]);
                    *(float2*)&sp[(rr+8)*64 + cc] = make_float2(acc[mi][ni][2], acc[mi][ni][3]);
                    acc[mi][ni][0] = 0.f; acc[mi][ni][1] = 0.f;
                    acc[mi][ni][2] = 0.f; acc[mi][ni][3] = 0.f;
                }
            }
        }
    }
}

// ======================= gate epilogue: 640 CTAs, 4 cols/thread, float4 =======================
__global__ __launch_bounds__(256) void gate_epi(
    const float* __restrict__ bias,
    const float* __restrict__ E,             // null unless layer 0
    const int* __restrict__ lettersT,        // letters + t, stride TT
    const float* __restrict__ stateIn,
    float* __restrict__ stateOut,
    __nv_bfloat16* __restrict__ Aout,
    const float* __restrict__ part,
    int writeX)
{
    int bx = blockIdx.x, tid = threadIdx.x;
    int tile = bx >> 3, sub = bx & 7;
    int tstart = tile * NCHT;

    int have = 1;
    int pp = ((tstart + 1) * PCTA - 1) / GITER;
    while (true){
        int epp = (pp + 1) * GITER / PCTA;
        if (epp >= tstart + NCHT) break;
        int c0 = epp - tstart;
        have |= 1 << ((c0 < 6) ? 1 : 2);
        pp++;
    }

    int tm = tile / 20, tn = tile % 20;
    int m0 = tm * 128 + sub * 16, n0g = tn * 64;
    const float* pb = part + (size_t)tile * 3 * 8192 + (size_t)sub * 16 * 64;

    int rl = tid >> 4;            // 0..15
    int cg = (tid & 15) * 4;      // 0..60
    int row = m0 + rl;
    int c = n0g + cg;

    // PDL prelaunch zone: bias + one-hot row are independent of gate_gemm
    float4 bz = *(const float4*)(bias + c);
    float e0 = 0.f, e1 = 0.f, e2 = 0.f, e3 = 0.f;
    if (E){
        float4 ez = *(const float4*)(E + (size_t)lettersT[row*TT] * NPG + c);
        e0 = ez.x; e1 = ez.y; e2 = ez.z; e3 = ez.w;
    }

#if __CUDA_ARCH__ >= 900
    cudaGridDependencySynchronize();         // part must be fully written by gate_gemm
#endif

    const float* base = pb + rl*64 + cg;
    float4 t0 = make_float4(0.f,0.f,0.f,0.f), t1 = t0, t2 = t0;
    if (have & 1) t0 = *(const float4*)(base);
    if (have & 2) t1 = *(const float4*)(base + 8192);
    if (have & 4) t2 = *(const float4*)(base + 16384);
    float z0 = t0.x + t1.x + t2.x + bz.x + e0;
    float z1 = t0.y + t1.y + t2.y + bz.y + e1;
    float z2 = t0.z + t1.z + t2.z + bz.z + e2;
    float z3 = t0.w + t1.w + t2.w + bz.w + e3;

    __nv_bfloat16* AoutLo = Aout + (size_t)BB*KB2;
    if (c < 1000){
        int j = c >> 1;
        float2 mo = *(const float2*)(stateIn + (size_t)row*SWID + 250 + j);
        float sg0 = fsig(z0), sg1 = fsig(z2);
        float mn0 = mo.x*sg0 + ftanh(z1)*(1.f - sg0);
        float mn1 = mo.y*sg1 + ftanh(z3)*(1.f - sg1);
        *(float2*)(stateOut + (size_t)row*SWID + 250 + j) = make_float2(mn0, mn1);
        __nv_bfloat162 h = __floats2bfloat162_rn(mn0, mn1);
        *(__nv_bfloat162*)(Aout + (size_t)row*KB2 + 250 + j) = h;
        float lo0 = mn0 - __bfloat162float(__low2bfloat16(h));
        float lo1 = mn1 - __bfloat162float(__high2bfloat16(h));
        *(__nv_bfloat162*)(AoutLo + (size_t)row*KB2 + 250 + j) = __floats2bfloat162_rn(lo0, lo1);
    } else if (c < 1250){
        int k = c - 1000;
        if (c + 3 < 1250){
            float x0 = ftanh(z0), x1 = ftanh(z1), x2 = ftanh(z2), x3 = ftanh(z3);
            if (writeX) *(float4*)(stateOut + (size_t)row*SWID + k) = make_float4(x0,x1,x2,x3);
            __nv_bfloat162 h01 = __floats2bfloat162_rn(x0, x1);
            __nv_bfloat162 h23 = __floats2bfloat162_rn(x2, x3);
            uint2 hv = make_uint2(*(uint32_t*)&h01, *(uint32_t*)&h23);
            *(uint2*)(Aout + (size_t)row*KB2 + k) = hv;
            float l0 = x0 - __bfloat162float(__low2bfloat16(h01));
            float l1 = x1 - __bfloat162float(__high2bfloat16(h01));
            float l2 = x2 - __bfloat162float(__low2bfloat16(h23));
            float l3 = x3 - __bfloat162float(__high2bfloat16(h23));
            __nv_bfloat162 q01 = __floats2bfloat162_rn(l0, l1);
            __nv_bfloat162 q23 = __floats2bfloat162_rn(l2, l3);
            uint2 lv = make_uint2(*(uint32_t*)&q01, *(uint32_t*)&q23);
            *(uint2*)(AoutLo + (size_t)row*KB2 + k) = lv;
        } else {
            float x0 = ftanh(z0), x1 = ftanh(z1);
            if (writeX) *(float2*)(stateOut + (size_t)row*SWID + k) = make_float2(x0, x1);
            __nv_bfloat162 h = __floats2bfloat162_rn(x0, x1);
            *(__nv_bfloat162*)(Aout + (size_t)row*KB2 + k) = h;
            float l0 = x0 - __bfloat162float(__low2bfloat16(h));
            float l1 = x1 - __bfloat162float(__high2bfloat16(h));
            *(__nv_bfloat162*)(AoutLo + (size_t)row*KB2 + k) = __floats2bfloat162_rn(l0, l1);
        }
    }
}

// ======================= head GEMM (fp32 f32x2, 32x64 tiles) =======================
__device__ __forceinline__ unsigned long long dup_f32x2(float x){
    unsigned long long rr;
    asm("mov.b64 %0, {%1, %1};" : "=l"(rr) : "f"(x));
    return rr;
}
__device__ __forceinline__ void fma_f32x2(unsigned long long& d, unsigned long long a, unsigned long long b){
    asm("fma.rn.f32x2 %0, %1, %2, %0;" : "+l"(d) : "l"(a), "l"(b));
}
__device__ __forceinline__ float2 unpack_f32x2(unsigned long long v){
    float2 f;
    asm("mov.b64 {%0, %1}, %2;" : "=f"(f.x), "=f"(f.y) : "l"(v));
    return f;
}

template<int MODE>   // 1: tanh, 2: identity
__global__ __launch_bounds__(256) void head_gemm(
    const float* __restrict__ A, int lda,
    const float* __restrict__ W, int nld,
    const float* __restrict__ bias,
    int K,
    float* __restrict__ out, int ldo)
{
    __shared__ __align__(16) float As[2][16][36];
    __shared__ __align__(16) float Bs[2][16][64];

    int tid = threadIdx.x;
    int tx = tid & 15, ty = tid >> 4;
    int m0 = blockIdx.y * 32, n0 = blockIdx.x * 64;

    unsigned long long acc[2][2];
    acc[0][0] = 0ULL; acc[0][1] = 0ULL; acc[1][0] = 0ULL; acc[1][1] = 0ULL;

    int ar = tid >> 2;
    int ak = (tid & 3) * 4;
    int br = tid >> 4;
    int bc = (tid & 15) * 4;

    const float* Ap = A + (size_t)(m0 + (ar & 31)) * lda + ak;
    const float* Wp = W + (size_t)br * nld + n0 + bc;

    {
        if (tid < 128){
            float4 a = *(const float4*)Ap;
            As[0][ak+0][ar] = a.x; As[0][ak+1][ar] = a.y;
            As[0][ak+2][ar] = a.z; As[0][ak+3][ar] = a.w;
        }
        float4 b = *(const float4*)Wp;
        *(float4*)&Bs[0][br][bc] = b;
    }
    __syncthreads();

    int nk = K >> 4;
    for (int kt = 0; kt < nk; kt++){
        int cur = kt & 1;
        float4 an, bn;
        if (kt + 1 < nk){
            if (tid < 128) an = *(const float4*)(Ap + (kt+1)*16);
            bn = *(const float4*)(Wp + (size_t)(kt+1)*16*nld);
        }
        #pragma unroll
        for (int k = 0; k < 16; k++){
            ulonglong2 bp = *(const ulonglong2*)&Bs[cur][k][tx*4];
            float a0 = As[cur][k][ty*2+0];
            float a1 = As[cur][k][ty*2+1];
            unsigned long long d0 = dup_f32x2(a0);
            unsigned long long d1 = dup_f32x2(a1);
            fma_f32x2(acc[0][0], d0, bp.x); fma_f32x2(acc[0][1], d0, bp.y);
            fma_f32x2(acc[1][0], d1, bp.x); fma_f32x2(acc[1][1], d1, bp.y);
        }
        if (kt + 1 < nk){
            __syncthreads();
            int nxt = cur ^ 1;
            if (tid < 128){
                As[nxt][ak+0][ar] = an.x; As[nxt][ak+1][ar] = an.y;
                As[nxt][ak+2][ar] = an.z; As[nxt][ak+3][ar] = an.w;
            }
            *(float4*)&Bs[nxt][br][bc] = bn;
            __syncthreads();
        }
    }

    #pragma unroll
    for (int i = 0; i < 2; i++){
        int rr = m0 + ty*2 + i;
        #pragma unroll
        for (int j2 = 0; j2 < 2; j2++){
            int c = n0 + tx*4 + j2*2;
            float2 z = unpack_f32x2(acc[i][j2]);
            z.x += bias[c]; z.y += bias[c+1];
            if (MODE == 1){
                out[(size_t)rr*ldo + c]   = tanhf(z.x);
                out[(size_t)rr*ldo + c+1] = tanhf(z.y);
            } else {
                out[(size_t)rr*ldo + c]   = z.x;
                out[(size_t)rr*ldo + c+1] = z.y;
            }
        }
    }
}

// -------- softmax over 30 classes --------
__global__ void softmax_k(const float* __restrict__ logits, float* __restrict__ out){
    int gw = blockIdx.x * 8 + (threadIdx.x >> 5);
    int lane = threadIdx.x & 31;
    if (gw >= BB) return;
    float v = (lane < VV) ? logits[gw*64 + lane] : -3.0e38f;
    float mx = v;
    #pragma unroll
    for (int o = 16; o > 0; o >>= 1) mx = fmaxf(mx, __shfl_xor_sync(0xffffffffu, mx, o));
    float ee = (lane < VV) ? expf(v - mx) : 0.f;
    float sm = ee;
    #pragma unroll
    for (int o = 16; o > 0; o >>= 1) sm += __shfl_xor_sync(0xffffffffu, sm, o);
    if (lane < VV) out[gw*VV + lane] = ee / sm;
}

extern "C" void kernel_launch(void* const* d_in, const int* in_sizes, int n_in,
                              void* d_out, int out_size)
{
    (void)in_sizes; (void)n_in; (void)out_size;
    const int*   letters = (const int*)  d_in[0];
    const float* w1_sv   = (const float*)d_in[1];
    const float* b1_sv   = (const float*)d_in[2];
    const float* w1_mem  = (const float*)d_in[3];
    const float* b1_mem  = (const float*)d_in[4];
    const float* w1_sw   = (const float*)d_in[5];
    const float* b1_sw   = (const float*)d_in[6];
    const float* w_sv    = (const float*)d_in[7];
    const float* b_sv    = (const float*)d_in[8];
    const float* w_mem   = (const float*)d_in[9];
    const float* b_mem   = (const float*)d_in[10];
    const float* w_sw    = (const float*)d_in[11];
    const float* b_sw    = (const float*)d_in[12];
    const float* wp1     = (const float*)d_in[13];
    const float* bp1     = (const float*)d_in[14];
    const float* wp2     = (const float*)d_in[15];
    const float* bp2     = (const float*)d_in[16];
    const float* wp3     = (const float*)d_in[17];
    const float* bp3     = (const float*)d_in[18];
    const float* wp4     = (const float*)d_in[19];
    const float* bp4     = (const float*)d_in[20];
    const float* wp5     = (const float*)d_in[21];
    const float* bp5     = (const float*)d_in[22];

    static int smem_cfg = 0;
    if (!smem_cfg){
        cudaFuncSetAttribute(gate_gemm, cudaFuncAttributeMaxDynamicSharedMemorySize, DSM_BYTES);
        smem_cfg = 1;
    }

    __nv_bfloat16 *pWt, *pAbf;
    float *pBias, *pE, *pState, *pH0, *pH1, *pLog, *pWH, *pBH, *pPart;
    cudaGetSymbolAddress((void**)&pWt,    g_Wt);
    cudaGetSymbolAddress((void**)&pAbf,   g_Abf);
    cudaGetSymbolAddress((void**)&pBias,  g_bias);
    cudaGetSymbolAddress((void**)&pE,     g_E);
    cudaGetSymbolAddress((void**)&pState, g_state);
    cudaGetSymbolAddress((void**)&pH0,    g_h0);
    cudaGetSymbolAddress((void**)&pH1,    g_h1);
    cudaGetSymbolAddress((void**)&pLog,   g_logits);
    cudaGetSymbolAddress((void**)&pWH,    g_WH);
    cudaGetSymbolAddress((void**)&pBH,    g_bH);
    cudaGetSymbolAddress((void**)&pPart,  g_part);

    // pack weights (tiled transpose, hi/lo planes) + misc + zero state/activations
    {
        pack_wt<<<dim3(KB2/64, NPG/64, 6), 256>>>(w1_sv, w1_mem, w1_sw, w_sv, w_mem, w_sw);
        long long S5 = 6*NPG + VV*NPG + 2*BB*SWID + WH_TOT + (512+320+256+128+64) + 2LL*2*BB*KB2/2;
        pack_misc<<<(unsigned)((S5 + 255) / 256), 256>>>(b1_sv, b1_mem, b1_sw, b_sv, b_mem, b_sw,
                                                         w1_sv, w1_mem, w1_sw,
                                                         wp1, bp1, wp2, bp2, wp3, bp3, wp4, bp4, wp5, bp5);
    }

    // PDL launch configs for the gate chain
    cudaLaunchAttribute pdlAttr[1];
    pdlAttr[0].id = cudaLaunchAttributeProgrammaticStreamSerialization;
    pdlAttr[0].val.programmaticStreamSerializationAllowed = 1;

    cudaLaunchConfig_t cfgG = {};
    cfgG.gridDim = dim3(PCTA, 1, 1);
    cfgG.blockDim = dim3(256, 1, 1);
    cfgG.dynamicSmemBytes = DSM_BYTES;
    cfgG.attrs = pdlAttr;
    cfgG.numAttrs = 1;

    cudaLaunchConfig_t cfgE = {};
    cfgE.gridDim = dim3(NT*8, 1, 1);
    cfgE.blockDim = dim3(256, 1, 1);
    cfgE.dynamicSmemBytes = 0;
    cfgE.attrs = pdlAttr;
    cfgE.numAttrs = 1;

    // 24 steps x 6 gates: pure stream-K GEMM + wide vectorized epilogue (PDL-chained,
    // weight/bias prefetch hoisted into the prelaunch zone)
    for (int g = 0; g < TT*6; g++){
        int t = g / 6, l = g % 6;
        int cur = g & 1, nxt = cur ^ 1;
        const float* Ept = (l == 0) ? pE : nullptr;
        const int*   lt  = (l == 0) ? letters + t : letters;
        cudaLaunchKernelEx(&cfgG, gate_gemm,
            (const __nv_bfloat16*)(pAbf + (size_t)cur*2*BB*KB2),
            (const __nv_bfloat16*)(pWt  + (size_t)l*2*NPG*KB2),
            pPart);
        cudaLaunchKernelEx(&cfgE, gate_epi,
            (const float*)(pBias + (size_t)l*NPG),
            (const float*)Ept, (const int*)lt,
            (const float*)(pState + (size_t)cur*BB*SWID),
            pState + (size_t)nxt*BB*SWID,
            pAbf + (size_t)nxt*2*BB*KB2,
            (const float*)pPart,
            (g == TT*6-1) ? 1 : 0);
    }

    // head: 750->450->300->200->100->30 (padded), 32-row tiles for occupancy
    head_gemm<1><<<dim3(8,16), 256>>>(pState, SWID, pWH,                   512, pBH,      752, pH0, 512);
    head_gemm<1><<<dim3(5,16), 256>>>(pH0,    512,  pWH + HW1,             320, pBH+512,  512, pH1, 320);
    head_gemm<1><<<dim3(4,16), 256>>>(pH1,    320,  pWH + HW1+HW2,         256, pBH+832,  320, pH0, 256);
    head_gemm<1><<<dim3(2,16), 256>>>(pH0,    256,  pWH + HW1+HW2+HW3,     128, pBH+1088, 256, pH1, 128);
    head_gemm<2><<<dim3(1,16), 256>>>(pH1,    128,  pWH + HW1+HW2+HW3+HW4,  64, pBH+1216, 128, pLog, 64);

    softmax_k<<<BB/8, 256>>>(pLog, (float*)d_out);
}